// round 4
// baseline (speedup 1.0000x reference)
#include <cuda_runtime.h>
#include <cuda_bf16.h>
#include <cuda_fp16.h>
#include <math.h>

#define T_ 16
#define B_ 1024
#define F_DIM 512
#define H_ 128
#define L_ 512
#define C_ 100
#define FSPLIT 4
#define KSPLIT (T_ * FSPLIT)

// Scratch (static device globals -- no allocation allowed)
__device__ __nv_bfloat16 g_h[(size_t)T_ * B_ * H_];       // 4 MB
__device__ __nv_bfloat16 g_mu[(size_t)T_ * B_ * L_];      // 16 MB
__device__ __nv_bfloat16 g_leafp[(size_t)T_ * L_ * C_];   // 1.6 MB
__device__ float g_part[(size_t)KSPLIT * B_ * C_];        // 26 MB

__device__ __forceinline__ unsigned pkf(float lo, float hi) {
    __nv_bfloat162 h = __floats2bfloat162_rn(lo, hi);
    return *reinterpret_cast<unsigned*>(&h);
}

__device__ __forceinline__ void mma_bf16(float* d, const unsigned* a, const unsigned* b) {
    asm volatile(
        "mma.sync.aligned.m16n8k16.row.col.f32.bf16.bf16.f32 "
        "{%0,%1,%2,%3}, {%4,%5,%6,%7}, {%8,%9}, {%0,%1,%2,%3};\n"
        : "+f"(d[0]), "+f"(d[1]), "+f"(d[2]), "+f"(d[3])
        : "r"(a[0]), "r"(a[1]), "r"(a[2]), "r"(a[3]), "r"(b[0]), "r"(b[1]));
}

// ---------------------------------------------------------------------------
// Stage 1: h = relu(feat @ W1 + b1), bf16 mma, out bf16.
// 64x128 tile, BK=32, 256 threads. grid (B/64, 1, T) = 256 CTAs
// ---------------------------------------------------------------------------
__global__ __launch_bounds__(256) void gemm1_bf16(const float* __restrict__ feat,
                                                  const float* __restrict__ W1,
                                                  const float* __restrict__ b1) {
    __shared__ unsigned As[64][20];    // bf16x2 pairs over k (16 kp + pad 4)
    __shared__ unsigned Bs[16][132];   // [kp][n], pad 4

    const int tid = threadIdx.x;
    const int wid = tid >> 5, lane = tid & 31;
    const int warp_m = wid >> 2, warp_n = wid & 3;   // 2 x 4 warps, 32x32 tiles
    const int lq = lane >> 2, lr = lane & 3;
    const int t = blockIdx.z;
    const int b0 = blockIdx.x * 64;

    const float* Wb = W1 + (size_t)t * F_DIM * H_;
    const float* bb = b1 + (size_t)t * H_;

    float acc[2][4][4];
#pragma unroll
    for (int i = 0; i < 2; i++)
#pragma unroll
        for (int j = 0; j < 4; j++)
#pragma unroll
            for (int q = 0; q < 4; q++) acc[i][j][q] = 0.0f;

    for (int k0 = 0; k0 < F_DIM; k0 += 32) {
        // A: 64x32 fp32 -> bf16 pairs. 512 float4 tasks, 2 per thread.
#pragma unroll
        for (int i = 0; i < 2; i++) {
            int e = tid + i * 256;
            int r = e >> 3, c4 = e & 7;
            float4 v = *reinterpret_cast<const float4*>(&feat[(size_t)(b0 + r) * F_DIM + k0 + c4 * 4]);
            As[r][c4 * 2] = pkf(v.x, v.y);
            As[r][c4 * 2 + 1] = pkf(v.z, v.w);
        }
        // B: pairs over k (strided rows). 512 tasks (kp, n4).
#pragma unroll
        for (int i = 0; i < 2; i++) {
            int e = tid + i * 256;
            int kp = e >> 5, n4 = e & 31;
            const float* r0 = Wb + (size_t)(k0 + 2 * kp) * H_ + n4 * 4;
            float4 x = *reinterpret_cast<const float4*>(r0);
            float4 y = *reinterpret_cast<const float4*>(r0 + H_);
            Bs[kp][n4 * 4 + 0] = pkf(x.x, y.x);
            Bs[kp][n4 * 4 + 1] = pkf(x.y, y.y);
            Bs[kp][n4 * 4 + 2] = pkf(x.z, y.z);
            Bs[kp][n4 * 4 + 3] = pkf(x.w, y.w);
        }
        __syncthreads();

#pragma unroll
        for (int kt = 0; kt < 2; kt++) {
            const int kb = kt * 8;
            unsigned afr[2][4], bfr[4][2];
#pragma unroll
            for (int im = 0; im < 2; im++) {
                int r = warp_m * 32 + im * 16;
                afr[im][0] = As[r + lq][kb + lr];
                afr[im][1] = As[r + 8 + lq][kb + lr];
                afr[im][2] = As[r + lq][kb + 4 + lr];
                afr[im][3] = As[r + 8 + lq][kb + 4 + lr];
            }
#pragma unroll
            for (int jn = 0; jn < 4; jn++) {
                int c = warp_n * 32 + jn * 8 + lq;
                bfr[jn][0] = Bs[kb + lr][c];
                bfr[jn][1] = Bs[kb + 4 + lr][c];
            }
#pragma unroll
            for (int im = 0; im < 2; im++)
#pragma unroll
                for (int jn = 0; jn < 4; jn++) mma_bf16(acc[im][jn], afr[im], bfr[jn]);
        }
        __syncthreads();
    }

    unsigned* gh = reinterpret_cast<unsigned*>(g_h);
#pragma unroll
    for (int im = 0; im < 2; im++) {
#pragma unroll
        for (int half = 0; half < 2; half++) {
            int r = warp_m * 32 + im * 16 + half * 8 + lq;
#pragma unroll
            for (int jn = 0; jn < 4; jn++) {
                int c = warp_n * 32 + jn * 8 + lr * 2;
                float x0 = fmaxf(acc[im][jn][half * 2 + 0] + bb[c], 0.0f);
                float x1 = fmaxf(acc[im][jn][half * 2 + 1] + bb[c + 1], 0.0f);
                gh[((size_t)t * B_ + b0 + r) * (H_ / 2) + (c >> 1)] = pkf(x0, x1);
            }
        }
    }
}

// ---------------------------------------------------------------------------
// Stage 2 fused: p = sigmoid(h @ W2 + b2) staged in fp16 smem, then
// mu routing products via tree-doubling, written bf16.
// One CTA: 64 b-rows x full L=512. grid (B/64, T) = 256 CTAs, 256 thr.
// ---------------------------------------------------------------------------
#define SM2_HA (64 * 68)
#define SM2_BS (16 * 132)
#define SM2_BYTES ((SM2_HA + SM2_BS) * 4 + 64 * 520 * 2)

__global__ __launch_bounds__(256) void stage2_fused(const float* __restrict__ W2,
                                                    const float* __restrict__ b2) {
    extern __shared__ unsigned smemu[];
    unsigned* hA = smemu;                              // [64][68]
    unsigned* Bs = smemu + SM2_HA;                     // [16][132]
    __half* ph = reinterpret_cast<__half*>(smemu + SM2_HA + SM2_BS);  // [64][520]

    const int tid = threadIdx.x;
    const int wid = tid >> 5, lane = tid & 31;
    const int warp_m = wid >> 2, warp_n = wid & 3;
    const int lq = lane >> 2, lr = lane & 3;
    const int t = blockIdx.y;
    const int b0 = blockIdx.x * 64;

    // Load h tile (64 x 128 bf16 = 64 x 64 u32), resident for all chunks.
    const unsigned* hsrc = reinterpret_cast<const unsigned*>(g_h) + ((size_t)t * B_ + b0) * (H_ / 2);
#pragma unroll
    for (int i = 0; i < 4; i++) {
        int e = tid + i * 256;
        int r = e >> 4, q = e & 15;
        uint4 v = *reinterpret_cast<const uint4*>(&hsrc[(size_t)r * 64 + q * 4]);
        *reinterpret_cast<uint4*>(&hA[r * 68 + q * 4]) = v;
    }
    __syncthreads();

    const float* W2t = W2 + (size_t)t * H_ * L_;
    const float* bbt = b2 + (size_t)t * L_;

#pragma unroll 1
    for (int chunk = 0; chunk < 4; chunk++) {
        const int n0c = chunk * 128;
        float acc[2][4][4];
#pragma unroll
        for (int i = 0; i < 2; i++)
#pragma unroll
            for (int j = 0; j < 4; j++)
#pragma unroll
                for (int q = 0; q < 4; q++) acc[i][j][q] = 0.0f;

#pragma unroll 1
        for (int k0s = 0; k0s < 4; k0s++) {
            const int k0 = k0s * 32;
#pragma unroll
            for (int i = 0; i < 2; i++) {
                int e = tid + i * 256;
                int kp = e >> 5, n4 = e & 31;
                const float* r0 = W2t + (size_t)(k0 + 2 * kp) * L_ + n0c + n4 * 4;
                float4 x = *reinterpret_cast<const float4*>(r0);
                float4 y = *reinterpret_cast<const float4*>(r0 + L_);
                Bs[kp * 132 + n4 * 4 + 0] = pkf(x.x, y.x);
                Bs[kp * 132 + n4 * 4 + 1] = pkf(x.y, y.y);
                Bs[kp * 132 + n4 * 4 + 2] = pkf(x.z, y.z);
                Bs[kp * 132 + n4 * 4 + 3] = pkf(x.w, y.w);
            }
            __syncthreads();
#pragma unroll
            for (int kt = 0; kt < 2; kt++) {
                const int kbG = k0s * 16 + kt * 8;
                const int kbB = kt * 8;
                unsigned afr[2][4], bfr[4][2];
#pragma unroll
                for (int im = 0; im < 2; im++) {
                    int r = warp_m * 32 + im * 16;
                    afr[im][0] = hA[(r + lq) * 68 + kbG + lr];
                    afr[im][1] = hA[(r + 8 + lq) * 68 + kbG + lr];
                    afr[im][2] = hA[(r + lq) * 68 + kbG + 4 + lr];
                    afr[im][3] = hA[(r + 8 + lq) * 68 + kbG + 4 + lr];
                }
#pragma unroll
                for (int jn = 0; jn < 4; jn++) {
                    int c = warp_n * 32 + jn * 8 + lq;
                    bfr[jn][0] = Bs[(kbB + lr) * 132 + c];
                    bfr[jn][1] = Bs[(kbB + 4 + lr) * 132 + c];
                }
#pragma unroll
                for (int im = 0; im < 2; im++)
#pragma unroll
                    for (int jn = 0; jn < 4; jn++) mma_bf16(acc[im][jn], afr[im], bfr[jn]);
            }
            __syncthreads();
        }

        // Epilogue: sigmoid -> ph (fp16)
#pragma unroll
        for (int im = 0; im < 2; im++) {
#pragma unroll
            for (int half = 0; half < 2; half++) {
                int r = warp_m * 32 + im * 16 + half * 8 + lq;
#pragma unroll
                for (int jn = 0; jn < 4; jn++) {
                    int c = warp_n * 32 + jn * 8 + lr * 2;
                    float x0 = 1.0f / (1.0f + __expf(-(acc[im][jn][half * 2 + 0] + bbt[n0c + c])));
                    float x1 = 1.0f / (1.0f + __expf(-(acc[im][jn][half * 2 + 1] + bbt[n0c + c + 1])));
                    *reinterpret_cast<__half2*>(&ph[r * 520 + n0c + c]) = __floats2half2_rn(x0, x1);
                }
            }
        }
    }
    __syncthreads();

    // mu phase: 64 rows x 16 leaf-blocks = 1024 tasks, 4 per thread.
    unsigned* muout = reinterpret_cast<unsigned*>(g_mu) + ((size_t)t * B_ + b0) * (L_ / 2);
#pragma unroll 1
    for (int i = 0; i < 4; i++) {
        int task = i * 256 + tid;
        int row = task >> 4;
        int l0 = (task & 15) << 5;
        const __half* sp = ph + row * 520;

        float pref = 1.0f;
#pragma unroll
        for (int d = 0; d < 4; d++) {
            int node = (1 << d) - 1 + (l0 >> (9 - d));
            float v = __half2float(sp[node]);
            pref *= ((l0 >> (8 - d)) & 1) ? (1.0f - v) : v;
        }

        float cur[32];
        cur[0] = pref;
#pragma unroll
        for (int d = 4; d <= 8; d++) {
            const int width = 1 << (d - 4);
            const int nbase = (1 << d) - 1 + (l0 >> (9 - d));
#pragma unroll
            for (int ii = width - 1; ii >= 0; ii--) {
                float v = __half2float(sp[nbase + ii]);
                float x = cur[ii];
                cur[2 * ii] = x * v;
                cur[2 * ii + 1] = x * (1.0f - v);
            }
        }

        unsigned w[16];
#pragma unroll
        for (int j = 0; j < 16; j++) w[j] = pkf(cur[2 * j], cur[2 * j + 1]);
        unsigned* dst = muout + (size_t)row * (L_ / 2) + (l0 >> 1);
#pragma unroll
        for (int j4 = 0; j4 < 4; j4++)
            *reinterpret_cast<uint4*>(dst + j4 * 4) =
                *reinterpret_cast<uint4*>(&w[j4 * 4]);
    }
}

// ---------------------------------------------------------------------------
// Leaf softmax: leafp[t,l,:] = softmax(pi[t,l,:]) -> bf16. One warp per row.
// ---------------------------------------------------------------------------
__global__ __launch_bounds__(128) void leaf_softmax_kernel(const float* __restrict__ pi) {
    const int row = blockIdx.x * 4 + (threadIdx.x >> 5);
    const int lane = threadIdx.x & 31;
    const float* pr = pi + (size_t)row * C_;

    float v[4];
#pragma unroll
    for (int j = 0; j < 4; j++) {
        int c = lane + j * 32;
        v[j] = (c < C_) ? pr[c] : -1e30f;
    }
    float m = fmaxf(fmaxf(v[0], v[1]), fmaxf(v[2], v[3]));
#pragma unroll
    for (int o = 16; o; o >>= 1) m = fmaxf(m, __shfl_xor_sync(0xffffffffu, m, o));

    float e[4];
    float s = 0.0f;
#pragma unroll
    for (int j = 0; j < 4; j++) {
        int c = lane + j * 32;
        e[j] = (c < C_) ? __expf(v[j] - m) : 0.0f;
        s += e[j];
    }
#pragma unroll
    for (int o = 16; o; o >>= 1) s += __shfl_xor_sync(0xffffffffu, s, o);
    float inv = 1.0f / s;
#pragma unroll
    for (int j = 0; j < 4; j++) {
        int c = lane + j * 32;
        if (c < C_) g_leafp[(size_t)row * C_ + c] = __float2bfloat16(e[j] * inv);
    }
}

// ---------------------------------------------------------------------------
// Final contraction: part[t*4+ks] = mu[t][:, ks*128:(ks+1)*128] @ leafp chunk.
// 64x128 tile, per-CTA K=128. grid (B/64, T, FSPLIT) = 1024 CTAs.
// ---------------------------------------------------------------------------
__global__ __launch_bounds__(256) void final_bf16() {
    __shared__ unsigned As[64][20];
    __shared__ unsigned Bs[16][132];

    const int tid = threadIdx.x;
    const int wid = tid >> 5, lane = tid & 31;
    const int warp_m = wid >> 2, warp_n = wid & 3;
    const int lq = lane >> 2, lr = lane & 3;
    const int t = blockIdx.y;
    const int ks = blockIdx.z;
    const int b0 = blockIdx.x * 64;
    const int kbase = ks * 128;

    const unsigned* mu_u = reinterpret_cast<const unsigned*>(g_mu) + ((size_t)t * B_ + b0) * (L_ / 2);
    const __nv_bfloat16* lp = g_leafp + (size_t)t * L_ * C_;

    float acc[2][4][4];
#pragma unroll
    for (int i = 0; i < 2; i++)
#pragma unroll
        for (int j = 0; j < 4; j++)
#pragma unroll
            for (int q = 0; q < 4; q++) acc[i][j][q] = 0.0f;

#pragma unroll 1
    for (int kk = 0; kk < 4; kk++) {
        const int k0 = kbase + kk * 32;
        // A: 64 rows x 16 u32 = 256 uint4 tasks, 1 per thread.
        {
            int r = tid >> 2, q = tid & 3;
            uint4 v = *reinterpret_cast<const uint4*>(&mu_u[(size_t)r * (L_ / 2) + (k0 >> 1) + q * 4]);
            *reinterpret_cast<uint4*>(&As[r][q * 4]) = v;
        }
        // B: leafp pairs over k, zero-pad col >= 100. 2048 tasks, 8 per thread.
#pragma unroll
        for (int i = 0; i < 8; i++) {
            int e = tid + i * 256;
            int kp = e >> 7, col = e & 127;
            unsigned val = 0;
            if (col < C_) {
                unsigned short lo = *reinterpret_cast<const unsigned short*>(&lp[(size_t)(k0 + 2 * kp) * C_ + col]);
                unsigned short hi = *reinterpret_cast<const unsigned short*>(&lp[(size_t)(k0 + 2 * kp + 1) * C_ + col]);
                val = (unsigned)lo | ((unsigned)hi << 16);
            }
            Bs[kp][col] = val;
        }
        __syncthreads();

#pragma unroll
        for (int kt = 0; kt < 2; kt++) {
            const int kb = kt * 8;
            unsigned afr[2][4], bfr[4][2];
#pragma unroll
            for (int im = 0; im < 2; im++) {
                int r = warp_m * 32 + im * 16;
                afr[im][0] = As[r + lq][kb + lr];
                afr[im][1] = As[r + 8 + lq][kb + lr];
                afr[im][2] = As[r + lq][kb + 4 + lr];
                afr[im][3] = As[r + 8 + lq][kb + 4 + lr];
            }
#pragma unroll
            for (int jn = 0; jn < 4; jn++) {
                int c = warp_n * 32 + jn * 8 + lq;
                bfr[jn][0] = Bs[kb + lr][c];
                bfr[jn][1] = Bs[kb + 4 + lr][c];
            }
#pragma unroll
            for (int im = 0; im < 2; im++)
#pragma unroll
                for (int jn = 0; jn < 4; jn++) mma_bf16(acc[im][jn], afr[im], bfr[jn]);
        }
        __syncthreads();
    }

    float* pb = g_part + (size_t)(t * FSPLIT + ks) * B_ * C_;
#pragma unroll
    for (int im = 0; im < 2; im++) {
#pragma unroll
        for (int half = 0; half < 2; half++) {
            int r = warp_m * 32 + im * 16 + half * 8 + lq;
#pragma unroll
            for (int jn = 0; jn < 4; jn++) {
                int c = warp_n * 32 + jn * 8 + lr * 2;
                if (c >= C_) continue;
                *reinterpret_cast<float2*>(&pb[(size_t)(b0 + r) * C_ + c]) =
                    make_float2(acc[im][jn][half * 2 + 0], acc[im][jn][half * 2 + 1]);
            }
        }
    }
}

// ---------------------------------------------------------------------------
// Deterministic reduction over KSPLIT partials + final log
// ---------------------------------------------------------------------------
__global__ __launch_bounds__(256) void reduce_log_kernel(float* __restrict__ out) {
    const int i = blockIdx.x * 256 + threadIdx.x;
    float s = 0.0f;
#pragma unroll
    for (int ks = 0; ks < KSPLIT; ks++) s += g_part[(size_t)ks * B_ * C_ + i];
    out[i] = logf(s * (1.0f / (float)(L_ * T_)));
}

extern "C" void kernel_launch(void* const* d_in, const int* in_sizes, int n_in,
                              void* d_out, int out_size) {
    const float* feat = (const float*)d_in[0];
    const float* W1 = (const float*)d_in[1];
    const float* b1 = (const float*)d_in[2];
    const float* W2 = (const float*)d_in[3];
    const float* b2 = (const float*)d_in[4];
    const float* pi = (const float*)d_in[5];
    float* out = (float*)d_out;

    cudaFuncSetAttribute(stage2_fused, cudaFuncAttributeMaxDynamicSharedMemorySize, SM2_BYTES);

    leaf_softmax_kernel<<<(T_ * L_) / 4, 128>>>(pi);
    gemm1_bf16<<<dim3(B_ / 64, 1, T_), 256>>>(feat, W1, b1);
    stage2_fused<<<dim3(B_ / 64, T_), 256, SM2_BYTES>>>(W2, b2);
    final_bf16<<<dim3(B_ / 64, T_, FSPLIT), 256>>>();
    reduce_log_kernel<<<(B_ * C_) / 256, 256>>>(out);
}

// round 5
// speedup vs baseline: 1.2289x; 1.2289x over previous
#include <cuda_runtime.h>
#include <cuda_bf16.h>
#include <cuda_fp16.h>
#include <math.h>

#define T_ 16
#define B_ 1024
#define F_DIM 512
#define H_ 128
#define L_ 512
#define C_ 100
#define FSPLIT 2
#define KSPLIT (T_ * FSPLIT)

// Scratch (static device globals -- no allocation allowed)
__device__ __nv_bfloat16 g_h[(size_t)T_ * B_ * H_];       // 4 MB
__device__ __nv_bfloat16 g_mu[(size_t)T_ * B_ * L_];      // 16 MB
__device__ unsigned g_lp[(size_t)T_ * (L_ / 2) * 128];    // 2 MB: packed leafp pairs
__device__ float g_part[(size_t)KSPLIT * B_ * C_];        // 13 MB

__device__ __forceinline__ unsigned pkf(float lo, float hi) {
    __nv_bfloat162 h = __floats2bfloat162_rn(lo, hi);
    return *reinterpret_cast<unsigned*>(&h);
}

__device__ __forceinline__ void mma_bf16(float* d, const unsigned* a, const unsigned* b) {
    asm volatile(
        "mma.sync.aligned.m16n8k16.row.col.f32.bf16.bf16.f32 "
        "{%0,%1,%2,%3}, {%4,%5,%6,%7}, {%8,%9}, {%0,%1,%2,%3};\n"
        : "+f"(d[0]), "+f"(d[1]), "+f"(d[2]), "+f"(d[3])
        : "r"(a[0]), "r"(a[1]), "r"(a[2]), "r"(a[3]), "r"(b[0]), "r"(b[1]));
}

__device__ __forceinline__ void cp16(void* s, const void* g) {
    unsigned sa = (unsigned)__cvta_generic_to_shared(s);
    asm volatile("cp.async.ca.shared.global [%0], [%1], 16;\n" :: "r"(sa), "l"(g));
}

// ---------------------------------------------------------------------------
// Stage 1: h = relu(feat @ W1 + b1), bf16 mma, out bf16.
// 64x128 tile, BK=32, 256 threads. grid (B/64, 1, T) = 256 CTAs
// ---------------------------------------------------------------------------
__global__ __launch_bounds__(256) void gemm1_bf16(const float* __restrict__ feat,
                                                  const float* __restrict__ W1,
                                                  const float* __restrict__ b1) {
    __shared__ unsigned As[64][20];
    __shared__ unsigned Bs[16][132];

    const int tid = threadIdx.x;
    const int wid = tid >> 5, lane = tid & 31;
    const int warp_m = wid >> 2, warp_n = wid & 3;
    const int lq = lane >> 2, lr = lane & 3;
    const int t = blockIdx.z;
    const int b0 = blockIdx.x * 64;

    const float* Wb = W1 + (size_t)t * F_DIM * H_;
    const float* bb = b1 + (size_t)t * H_;

    float acc[2][4][4];
#pragma unroll
    for (int i = 0; i < 2; i++)
#pragma unroll
        for (int j = 0; j < 4; j++)
#pragma unroll
            for (int q = 0; q < 4; q++) acc[i][j][q] = 0.0f;

    for (int k0 = 0; k0 < F_DIM; k0 += 32) {
#pragma unroll
        for (int i = 0; i < 2; i++) {
            int e = tid + i * 256;
            int r = e >> 3, c4 = e & 7;
            float4 v = *reinterpret_cast<const float4*>(&feat[(size_t)(b0 + r) * F_DIM + k0 + c4 * 4]);
            As[r][c4 * 2] = pkf(v.x, v.y);
            As[r][c4 * 2 + 1] = pkf(v.z, v.w);
        }
#pragma unroll
        for (int i = 0; i < 2; i++) {
            int e = tid + i * 256;
            int kp = e >> 5, n4 = e & 31;
            const float* r0 = Wb + (size_t)(k0 + 2 * kp) * H_ + n4 * 4;
            float4 x = *reinterpret_cast<const float4*>(r0);
            float4 y = *reinterpret_cast<const float4*>(r0 + H_);
            Bs[kp][n4 * 4 + 0] = pkf(x.x, y.x);
            Bs[kp][n4 * 4 + 1] = pkf(x.y, y.y);
            Bs[kp][n4 * 4 + 2] = pkf(x.z, y.z);
            Bs[kp][n4 * 4 + 3] = pkf(x.w, y.w);
        }
        __syncthreads();

#pragma unroll
        for (int kt = 0; kt < 2; kt++) {
            const int kb = kt * 8;
            unsigned afr[2][4], bfr[4][2];
#pragma unroll
            for (int im = 0; im < 2; im++) {
                int r = warp_m * 32 + im * 16;
                afr[im][0] = As[r + lq][kb + lr];
                afr[im][1] = As[r + 8 + lq][kb + lr];
                afr[im][2] = As[r + lq][kb + 4 + lr];
                afr[im][3] = As[r + 8 + lq][kb + 4 + lr];
            }
#pragma unroll
            for (int jn = 0; jn < 4; jn++) {
                int c = warp_n * 32 + jn * 8 + lq;
                bfr[jn][0] = Bs[kb + lr][c];
                bfr[jn][1] = Bs[kb + 4 + lr][c];
            }
#pragma unroll
            for (int im = 0; im < 2; im++)
#pragma unroll
                for (int jn = 0; jn < 4; jn++) mma_bf16(acc[im][jn], afr[im], bfr[jn]);
        }
        __syncthreads();
    }

    unsigned* gh = reinterpret_cast<unsigned*>(g_h);
#pragma unroll
    for (int im = 0; im < 2; im++) {
#pragma unroll
        for (int half = 0; half < 2; half++) {
            int r = warp_m * 32 + im * 16 + half * 8 + lq;
#pragma unroll
            for (int jn = 0; jn < 4; jn++) {
                int c = warp_n * 32 + jn * 8 + lr * 2;
                float x0 = fmaxf(acc[im][jn][half * 2 + 0] + bb[c], 0.0f);
                float x1 = fmaxf(acc[im][jn][half * 2 + 1] + bb[c + 1], 0.0f);
                gh[((size_t)t * B_ + b0 + r) * (H_ / 2) + (c >> 1)] = pkf(x0, x1);
            }
        }
    }
}

// ---------------------------------------------------------------------------
// Stage 2 fused: p = sigmoid(h @ W2 + b2) staged in fp16 smem, then
// mu routing products via tree-doubling, written bf16.
// One CTA: 64 b-rows x full L=512. grid (B/64, T) = 256 CTAs, 256 thr.
// ---------------------------------------------------------------------------
#define SM2_HA (64 * 68)
#define SM2_BS (16 * 132)
#define SM2_BYTES ((SM2_HA + SM2_BS) * 4 + 64 * 520 * 2)

__global__ __launch_bounds__(256) void stage2_fused(const float* __restrict__ W2,
                                                    const float* __restrict__ b2) {
    extern __shared__ unsigned smemu[];
    unsigned* hA = smemu;                              // [64][68]
    unsigned* Bs = smemu + SM2_HA;                     // [16][132]
    __half* ph = reinterpret_cast<__half*>(smemu + SM2_HA + SM2_BS);  // [64][520]

    const int tid = threadIdx.x;
    const int wid = tid >> 5, lane = tid & 31;
    const int warp_m = wid >> 2, warp_n = wid & 3;
    const int lq = lane >> 2, lr = lane & 3;
    const int t = blockIdx.y;
    const int b0 = blockIdx.x * 64;

    const unsigned* hsrc = reinterpret_cast<const unsigned*>(g_h) + ((size_t)t * B_ + b0) * (H_ / 2);
#pragma unroll
    for (int i = 0; i < 4; i++) {
        int e = tid + i * 256;
        int r = e >> 4, q = e & 15;
        uint4 v = *reinterpret_cast<const uint4*>(&hsrc[(size_t)r * 64 + q * 4]);
        *reinterpret_cast<uint4*>(&hA[r * 68 + q * 4]) = v;
    }
    __syncthreads();

    const float* W2t = W2 + (size_t)t * H_ * L_;
    const float* bbt = b2 + (size_t)t * L_;

#pragma unroll 1
    for (int chunk = 0; chunk < 4; chunk++) {
        const int n0c = chunk * 128;
        float acc[2][4][4];
#pragma unroll
        for (int i = 0; i < 2; i++)
#pragma unroll
            for (int j = 0; j < 4; j++)
#pragma unroll
                for (int q = 0; q < 4; q++) acc[i][j][q] = 0.0f;

#pragma unroll 1
        for (int k0s = 0; k0s < 4; k0s++) {
            const int k0 = k0s * 32;
#pragma unroll
            for (int i = 0; i < 2; i++) {
                int e = tid + i * 256;
                int kp = e >> 5, n4 = e & 31;
                const float* r0 = W2t + (size_t)(k0 + 2 * kp) * L_ + n0c + n4 * 4;
                float4 x = *reinterpret_cast<const float4*>(r0);
                float4 y = *reinterpret_cast<const float4*>(r0 + L_);
                Bs[kp * 132 + n4 * 4 + 0] = pkf(x.x, y.x);
                Bs[kp * 132 + n4 * 4 + 1] = pkf(x.y, y.y);
                Bs[kp * 132 + n4 * 4 + 2] = pkf(x.z, y.z);
                Bs[kp * 132 + n4 * 4 + 3] = pkf(x.w, y.w);
            }
            __syncthreads();
#pragma unroll
            for (int kt = 0; kt < 2; kt++) {
                const int kbG = k0s * 16 + kt * 8;
                const int kbB = kt * 8;
                unsigned afr[2][4], bfr[4][2];
#pragma unroll
                for (int im = 0; im < 2; im++) {
                    int r = warp_m * 32 + im * 16;
                    afr[im][0] = hA[(r + lq) * 68 + kbG + lr];
                    afr[im][1] = hA[(r + 8 + lq) * 68 + kbG + lr];
                    afr[im][2] = hA[(r + lq) * 68 + kbG + 4 + lr];
                    afr[im][3] = hA[(r + 8 + lq) * 68 + kbG + 4 + lr];
                }
#pragma unroll
                for (int jn = 0; jn < 4; jn++) {
                    int c = warp_n * 32 + jn * 8 + lq;
                    bfr[jn][0] = Bs[(kbB + lr) * 132 + c];
                    bfr[jn][1] = Bs[(kbB + 4 + lr) * 132 + c];
                }
#pragma unroll
                for (int im = 0; im < 2; im++)
#pragma unroll
                    for (int jn = 0; jn < 4; jn++) mma_bf16(acc[im][jn], afr[im], bfr[jn]);
            }
            __syncthreads();
        }

#pragma unroll
        for (int im = 0; im < 2; im++) {
#pragma unroll
            for (int half = 0; half < 2; half++) {
                int r = warp_m * 32 + im * 16 + half * 8 + lq;
#pragma unroll
                for (int jn = 0; jn < 4; jn++) {
                    int c = warp_n * 32 + jn * 8 + lr * 2;
                    float x0 = 1.0f / (1.0f + __expf(-(acc[im][jn][half * 2 + 0] + bbt[n0c + c])));
                    float x1 = 1.0f / (1.0f + __expf(-(acc[im][jn][half * 2 + 1] + bbt[n0c + c + 1])));
                    *reinterpret_cast<__half2*>(&ph[r * 520 + n0c + c]) = __floats2half2_rn(x0, x1);
                }
            }
        }
    }
    __syncthreads();

    // mu phase: 64 rows x 16 leaf-blocks = 1024 tasks, 4 per thread.
    unsigned* muout = reinterpret_cast<unsigned*>(g_mu) + ((size_t)t * B_ + b0) * (L_ / 2);
#pragma unroll 1
    for (int i = 0; i < 4; i++) {
        int task = i * 256 + tid;
        int row = task >> 4;
        int l0 = (task & 15) << 5;
        const __half* sp = ph + row * 520;

        float pref = 1.0f;
#pragma unroll
        for (int d = 0; d < 4; d++) {
            int node = (1 << d) - 1 + (l0 >> (9 - d));
            float v = __half2float(sp[node]);
            pref *= ((l0 >> (8 - d)) & 1) ? (1.0f - v) : v;
        }

        float cur[32];
        cur[0] = pref;
#pragma unroll
        for (int d = 4; d <= 8; d++) {
            const int width = 1 << (d - 4);
            const int nbase = (1 << d) - 1 + (l0 >> (9 - d));
#pragma unroll
            for (int ii = width - 1; ii >= 0; ii--) {
                float v = __half2float(sp[nbase + ii]);
                float x = cur[ii];
                cur[2 * ii] = x * v;
                cur[2 * ii + 1] = x * (1.0f - v);
            }
        }

        unsigned w[16];
#pragma unroll
        for (int j = 0; j < 16; j++) w[j] = pkf(cur[2 * j], cur[2 * j + 1]);
        unsigned* dst = muout + (size_t)row * (L_ / 2) + (l0 >> 1);
#pragma unroll
        for (int j4 = 0; j4 < 4; j4++)
            *reinterpret_cast<uint4*>(dst + j4 * 4) =
                *reinterpret_cast<uint4*>(&w[j4 * 4]);
    }
}

// ---------------------------------------------------------------------------
// Leaf softmax -> packed MMA-ready layout g_lp[t][l/2][128] (bf16x2 over l,
// zero-padded cols >= C_). One warp per (t,l) row; 16-bit half writes.
// ---------------------------------------------------------------------------
__global__ __launch_bounds__(128) void leaf_softmax_pack(const float* __restrict__ pi) {
    const int row = blockIdx.x * 4 + (threadIdx.x >> 5);   // t*L + l
    const int lane = threadIdx.x & 31;
    const int t = row >> 9, l = row & (L_ - 1);
    const float* pr = pi + (size_t)row * C_;

    float v[4];
#pragma unroll
    for (int j = 0; j < 4; j++) {
        int c = lane + j * 32;
        v[j] = (c < C_) ? pr[c] : -1e30f;
    }
    float m = fmaxf(fmaxf(v[0], v[1]), fmaxf(v[2], v[3]));
#pragma unroll
    for (int o = 16; o; o >>= 1) m = fmaxf(m, __shfl_xor_sync(0xffffffffu, m, o));

    float e[4];
    float s = 0.0f;
#pragma unroll
    for (int j = 0; j < 4; j++) {
        int c = lane + j * 32;
        e[j] = (c < C_) ? __expf(v[j] - m) : 0.0f;
        s += e[j];
    }
#pragma unroll
    for (int o = 16; o; o >>= 1) s += __shfl_xor_sync(0xffffffffu, s, o);
    float inv = 1.0f / s;

    unsigned short* base = reinterpret_cast<unsigned short*>(g_lp);
    const size_t rowbase = ((size_t)t * (L_ / 2) + (l >> 1)) * 128;
#pragma unroll
    for (int j = 0; j < 4; j++) {
        int c = lane + j * 32;
        __nv_bfloat16 bv = __float2bfloat16((c < C_) ? e[j] * inv : 0.0f);
        base[(rowbase + c) * 2 + (l & 1)] = *reinterpret_cast<unsigned short*>(&bv);
    }
}

// ---------------------------------------------------------------------------
// Final contraction: part[t*2+ks] = mu[t][:, ks*256:+256] @ leafp chunk.
// 128x128 tile, K=256 per CTA (8 k-tiles of 32), cp.async double-buffered.
// grid (B/128, T, FSPLIT) = 256 CTAs, 256 threads. Warp tile 64x32 (im<4).
// ---------------------------------------------------------------------------
__global__ __launch_bounds__(256) void final_bf16() {
    __shared__ unsigned As[2][128 * 20];
    __shared__ unsigned Bs[2][16 * 132];

    const int tid = threadIdx.x;
    const int wid = tid >> 5, lane = tid & 31;
    const int warp_m = wid >> 2, warp_n = wid & 3;   // 2x4 warps, 64x32 warp tiles
    const int lq = lane >> 2, lr = lane & 3;
    const int t = blockIdx.y;
    const int ks = blockIdx.z;
    const int b0 = blockIdx.x * 128;

    const unsigned* mu_u = reinterpret_cast<const unsigned*>(g_mu) + ((size_t)t * B_ + b0) * (L_ / 2);
    const unsigned* lpb = g_lp + (size_t)t * (L_ / 2) * 128;

    float acc[4][4][4];
#pragma unroll
    for (int i = 0; i < 4; i++)
#pragma unroll
        for (int j = 0; j < 4; j++)
#pragma unroll
            for (int q = 0; q < 4; q++) acc[i][j][q] = 0.0f;

    auto issue = [&](int kt, int buf) {
        const int kp0 = (ks * 256 + kt * 32) >> 1;   // pair-row base in packed k
        // A: 128 rows x 16 u32 = 512 uint4 chunks, 2 per thread
#pragma unroll
        for (int i = 0; i < 2; i++) {
            int e = tid + i * 256;
            int r = e >> 2, q = e & 3;
            cp16(&As[buf][r * 20 + q * 4], &mu_u[(size_t)r * (L_ / 2) + kp0 + q * 4]);
        }
        // B: contiguous 16 x 128 u32 block in packed leafp
#pragma unroll
        for (int i = 0; i < 2; i++) {
            int e = tid + i * 256;
            int kp = e >> 5, c4 = e & 31;
            cp16(&Bs[buf][kp * 132 + c4 * 4], &lpb[(size_t)(kp0 + kp) * 128 + c4 * 4]);
        }
        asm volatile("cp.async.commit_group;\n");
    };

    issue(0, 0);
#pragma unroll 1
    for (int kt = 0; kt < 8; kt++) {
        const int buf = kt & 1;
        if (kt < 7) {
            issue(kt + 1, buf ^ 1);
            asm volatile("cp.async.wait_group 1;\n");
        } else {
            asm volatile("cp.async.wait_group 0;\n");
        }
        __syncthreads();

#pragma unroll
        for (int kh = 0; kh < 2; kh++) {
            const int kb = kh * 8;
            unsigned bfr[4][2];
#pragma unroll
            for (int jn = 0; jn < 4; jn++) {
                int c = warp_n * 32 + jn * 8 + lq;
                bfr[jn][0] = Bs[buf][(kb + lr) * 132 + c];
                bfr[jn][1] = Bs[buf][(kb + 4 + lr) * 132 + c];
            }
#pragma unroll
            for (int im = 0; im < 4; im++) {
                int r = warp_m * 64 + im * 16;
                unsigned afr[4];
                afr[0] = As[buf][(r + lq) * 20 + kb + lr];
                afr[1] = As[buf][(r + 8 + lq) * 20 + kb + lr];
                afr[2] = As[buf][(r + lq) * 20 + kb + 4 + lr];
                afr[3] = As[buf][(r + 8 + lq) * 20 + kb + 4 + lr];
#pragma unroll
                for (int jn = 0; jn < 4; jn++) mma_bf16(acc[im][jn], afr, bfr[jn]);
            }
        }
        __syncthreads();
    }

    float* pb = g_part + (size_t)(t * FSPLIT + ks) * B_ * C_;
#pragma unroll
    for (int im = 0; im < 4; im++) {
#pragma unroll
        for (int half = 0; half < 2; half++) {
            int r = warp_m * 64 + im * 16 + half * 8 + lq;
#pragma unroll
            for (int jn = 0; jn < 4; jn++) {
                int c = warp_n * 32 + jn * 8 + lr * 2;
                if (c >= C_) continue;
                *reinterpret_cast<float2*>(&pb[(size_t)(b0 + r) * C_ + c]) =
                    make_float2(acc[im][jn][half * 2 + 0], acc[im][jn][half * 2 + 1]);
            }
        }
    }
}

// ---------------------------------------------------------------------------
// Deterministic reduction over KSPLIT partials + final log
// ---------------------------------------------------------------------------
__global__ __launch_bounds__(256) void reduce_log_kernel(float* __restrict__ out) {
    const int i = blockIdx.x * 256 + threadIdx.x;
    float s = 0.0f;
#pragma unroll
    for (int ks = 0; ks < KSPLIT; ks++) s += g_part[(size_t)ks * B_ * C_ + i];
    out[i] = logf(s * (1.0f / (float)(L_ * T_)));
}

extern "C" void kernel_launch(void* const* d_in, const int* in_sizes, int n_in,
                              void* d_out, int out_size) {
    const float* feat = (const float*)d_in[0];
    const float* W1 = (const float*)d_in[1];
    const float* b1 = (const float*)d_in[2];
    const float* W2 = (const float*)d_in[3];
    const float* b2 = (const float*)d_in[4];
    const float* pi = (const float*)d_in[5];
    float* out = (float*)d_out;

    cudaFuncSetAttribute(stage2_fused, cudaFuncAttributeMaxDynamicSharedMemorySize, SM2_BYTES);

    leaf_softmax_pack<<<(T_ * L_) / 4, 128>>>(pi);
    gemm1_bf16<<<dim3(B_ / 64, 1, T_), 256>>>(feat, W1, b1);
    stage2_fused<<<dim3(B_ / 64, T_), 256, SM2_BYTES>>>(W2, b2);
    final_bf16<<<dim3(B_ / 128, T_, FSPLIT), 256>>>();
    reduce_log_kernel<<<(B_ * C_) / 256, 256>>>(out);
}